// round 9
// baseline (speedup 1.0000x reference)
#include <cuda_runtime.h>

// Accumulators in __device__ globals (allocation-free scratch). Read AND reset
// by the last block each launch -> state invariant across graph replays.
__device__ double g_inter = 0.0;
__device__ double g_desire_sum = 0.0;
__device__ unsigned long long g_count = 0ull;
__device__ unsigned int g_ticket = 0u;

// Quarter-warp per row: 8 lanes x 4 float4 = one 128-float row.
// A warp processes a 4-row tile per iteration: 8 LDG.128/thread, then a
// single 3-deep shuffle chain reduces all 4 rows at once.
// Explicit double-buffering: next tile's loads issue BEFORE this tile's
// compute+shuffle, so the warp always has memory in flight.
// __ldcs: data is touched exactly once -> evict-first, don't pollute caches.
__global__ __launch_bounds__(256)
void fra_fused_kernel(const float4* __restrict__ o1,
                      const float4* __restrict__ o2,
                      const float*  __restrict__ desire,
                      float* __restrict__ out,
                      int n_rows) {
    const int lane = threadIdx.x & 31;
    const int wib  = threadIdx.x >> 5;
    const int wpb  = blockDim.x >> 5;
    const int wg   = blockIdx.x * wpb + wib;
    const int tw   = gridDim.x * wpb;

    const int g = lane >> 3;   // which row of the 4-row tile (0..3)
    const int j = lane & 7;    // float4 slot within row: j, j+8, j+16, j+24

    double       l_inter = 0.0, l_des = 0.0;
    unsigned int l_cnt = 0u;
    const float margin_sq = 0.390625f;   // (1.25/2)^2

    const int n_tiles = n_rows >> 2;

    float4 a0, a1, a2, a3, b0, b1, b2, b3;
    int tile = wg;
    if (tile < n_tiles) {
        const int base = (tile * 4 + g) * 32 + j;
        a0 = __ldcs(o1 + base);      b0 = __ldcs(o2 + base);
        a1 = __ldcs(o1 + base + 8);  b1 = __ldcs(o2 + base + 8);
        a2 = __ldcs(o1 + base + 16); b2 = __ldcs(o2 + base + 16);
        a3 = __ldcs(o1 + base + 24); b3 = __ldcs(o2 + base + 24);
    }

    while (tile < n_tiles) {
        const int next = tile + tw;
        float4 na0, na1, na2, na3, nb0, nb1, nb2, nb3;
        if (next < n_tiles) {          // prefetch next tile FIRST
            const int nb = (next * 4 + g) * 32 + j;
            na0 = __ldcs(o1 + nb);      nb0 = __ldcs(o2 + nb);
            na1 = __ldcs(o1 + nb + 8);  nb1 = __ldcs(o2 + nb + 8);
            na2 = __ldcs(o1 + nb + 16); nb2 = __ldcs(o2 + nb + 16);
            na3 = __ldcs(o1 + nb + 24); nb3 = __ldcs(o2 + nb + 24);
        }

        // 16 squared diffs, two independent FMA chains.
        float s0, s1, d;
        d = a0.x - b0.x; s0  = d * d;   d = a0.y - b0.y; s1  = d * d;
        d = a0.z - b0.z; s0 += d * d;   d = a0.w - b0.w; s1 += d * d;
        d = a1.x - b1.x; s0 += d * d;   d = a1.y - b1.y; s1 += d * d;
        d = a1.z - b1.z; s0 += d * d;   d = a1.w - b1.w; s1 += d * d;
        d = a2.x - b2.x; s0 += d * d;   d = a2.y - b2.y; s1 += d * d;
        d = a2.z - b2.z; s0 += d * d;   d = a2.w - b2.w; s1 += d * d;
        d = a3.x - b3.x; s0 += d * d;   d = a3.y - b3.y; s1 += d * d;
        d = a3.z - b3.z; s0 += d * d;   d = a3.w - b3.w; s1 += d * d;
        float s = s0 + s1;

        // One 3-deep chain reduces within each 8-lane group = all 4 rows.
        s += __shfl_xor_sync(0xffffffffu, s, 4);
        s += __shfl_xor_sync(0xffffffffu, s, 2);
        s += __shfl_xor_sync(0xffffffffu, s, 1);

        if (j == 0) {                  // lanes 0,8,16,24 own rows tile*4+g
            const float dsr = desire[tile * 4 + g];
            l_des += (double)dsr;
            if (s > margin_sq) { l_cnt += 1u; l_inter += (double)dsr; }
        }

        a0 = na0; a1 = na1; a2 = na2; a3 = na3;
        b0 = nb0; b1 = nb1; b2 = nb2; b3 = nb3;
        tile = next;
    }

    // Tail rows (n_rows % 4), handled by warp 0 only.
    if (wg == 0) {
        for (int row = n_tiles * 4; row < n_rows; row++) {
            float s = 0.0f;
            if (g == 0) {
                const int base = row * 32 + j;
                #pragma unroll
                for (int k = 0; k < 4; k++) {
                    const float4 a = o1[base + 8 * k];
                    const float4 b = o2[base + 8 * k];
                    const float dx = a.x - b.x, dy = a.y - b.y;
                    const float dz = a.z - b.z, dw = a.w - b.w;
                    s += dx * dx + dy * dy + dz * dz + dw * dw;
                }
            }
            s += __shfl_xor_sync(0xffffffffu, s, 4);
            s += __shfl_xor_sync(0xffffffffu, s, 2);
            s += __shfl_xor_sync(0xffffffffu, s, 1);
            if (lane == 0) {
                const float dsr = desire[row];
                l_des += (double)dsr;
                if (s > margin_sq) { l_cnt += 1u; l_inter += (double)dsr; }
            }
        }
    }

    // Warp reduction (accumulators live on the j==0 lanes; reduce all 32).
    #pragma unroll
    for (int off = 16; off > 0; off >>= 1) {
        l_inter += __shfl_xor_sync(0xffffffffu, l_inter, off);
        l_des   += __shfl_xor_sync(0xffffffffu, l_des,   off);
        l_cnt   += __shfl_xor_sync(0xffffffffu, l_cnt,   off);
    }

    __shared__ double       s_i[8], s_d[8];
    __shared__ unsigned int s_c[8];
    __shared__ bool         s_last;
    if (lane == 0) { s_i[wib] = l_inter; s_d[wib] = l_des; s_c[wib] = l_cnt; }
    __syncthreads();

    if (threadIdx.x == 0) {
        double       bi = 0.0, bd = 0.0;
        unsigned int bc = 0u;
        for (int w = 0; w < wpb; w++) { bi += s_i[w]; bd += s_d[w]; bc += s_c[w]; }
        atomicAdd(&g_inter, bi);
        atomicAdd(&g_desire_sum, bd);
        atomicAdd(&g_count, (unsigned long long)bc);
        __threadfence();
        s_last = (atomicAdd(&g_ticket, 1u) == gridDim.x - 1);
    }
    __syncthreads();

    if (s_last && threadIdx.x == 0) {
        __threadfence();
        const double inter = atomicAdd(&g_inter, 0.0);
        const double des   = atomicAdd(&g_desire_sum, 0.0);
        const double cnt   = (double)atomicAdd(&g_count, 0ull);
        const double uni   = cnt + des - inter;
        out[0] = (float)((inter + 1e-6) / (uni + 1e-6));
        g_inter = 0.0;
        g_desire_sum = 0.0;
        g_count = 0ull;
        __threadfence();
        g_ticket = 0u;
    }
}

extern "C" void kernel_launch(void* const* d_in, const int* in_sizes, int n_in,
                              void* d_out, int out_size) {
    const float4* o1     = (const float4*)d_in[0];
    const float4* o2     = (const float4*)d_in[1];
    const float*  desire = (const float*)d_in[2];
    float*        out    = (float*)d_out;

    const int n_rows = in_sizes[2];   // N = 262144

    // 444 = 148 SMs x 3 blocks: regs=78 admits 3 blocks/SM
    // (3*256*78 = 59904 <= 64K regs). One full wave, 24 warps/SM ->
    // ~96 KB of loads in flight per SM, 50% more than R8.
    fra_fused_kernel<<<444, 256>>>(o1, o2, desire, out, n_rows);
}

// round 10
// speedup vs baseline: 1.0061x; 1.0061x over previous
#include <cuda_runtime.h>

// Accumulators in __device__ globals (allocation-free scratch). Read AND reset
// by the last block each launch -> state invariant across graph replays.
__device__ double g_inter = 0.0;
__device__ double g_desire_sum = 0.0;
__device__ unsigned long long g_count = 0ull;
__device__ unsigned int g_ticket = 0u;

// Quarter-warp per row: 8 lanes x 4 float4 = one 128-float row; a warp owns a
// 4-row tile (4 KB) per stage. THREE pipeline stages: while computing tile i,
// tiles i+1 and i+2 are both in flight, so the LDG stream never drains during
// the compute/shuffle/accumulate block.

#define LOAD_TILE(t, A0, A1, A2, A3, B0, B1, B2, B3)                     \
    do {                                                                 \
        if ((t) < n_tiles) {                                             \
            const int _b = ((t) * 4 + g) * 32 + j;                       \
            A0 = __ldcs(o1 + _b);      B0 = __ldcs(o2 + _b);             \
            A1 = __ldcs(o1 + _b + 8);  B1 = __ldcs(o2 + _b + 8);         \
            A2 = __ldcs(o1 + _b + 16); B2 = __ldcs(o2 + _b + 16);        \
            A3 = __ldcs(o1 + _b + 24); B3 = __ldcs(o2 + _b + 24);        \
        }                                                                \
    } while (0)

#define COMPUTE_TILE(t, A0, A1, A2, A3, B0, B1, B2, B3)                  \
    do {                                                                 \
        float _s0, _s1, _d;                                              \
        _d = A0.x - B0.x; _s0  = _d * _d;  _d = A0.y - B0.y; _s1  = _d * _d; \
        _d = A0.z - B0.z; _s0 += _d * _d;  _d = A0.w - B0.w; _s1 += _d * _d; \
        _d = A1.x - B1.x; _s0 += _d * _d;  _d = A1.y - B1.y; _s1 += _d * _d; \
        _d = A1.z - B1.z; _s0 += _d * _d;  _d = A1.w - B1.w; _s1 += _d * _d; \
        _d = A2.x - B2.x; _s0 += _d * _d;  _d = A2.y - B2.y; _s1 += _d * _d; \
        _d = A2.z - B2.z; _s0 += _d * _d;  _d = A2.w - B2.w; _s1 += _d * _d; \
        _d = A3.x - B3.x; _s0 += _d * _d;  _d = A3.y - B3.y; _s1 += _d * _d; \
        _d = A3.z - B3.z; _s0 += _d * _d;  _d = A3.w - B3.w; _s1 += _d * _d; \
        float _s = _s0 + _s1;                                            \
        _s += __shfl_xor_sync(0xffffffffu, _s, 4);                       \
        _s += __shfl_xor_sync(0xffffffffu, _s, 2);                       \
        _s += __shfl_xor_sync(0xffffffffu, _s, 1);                       \
        if (j == 0) {                                                    \
            const float _dsr = desire[(t) * 4 + g];                      \
            l_des += (double)_dsr;                                       \
            if (_s > margin_sq) { l_cnt += 1u; l_inter += (double)_dsr; }\
        }                                                                \
    } while (0)

__global__ __launch_bounds__(256, 2)
void fra_fused_kernel(const float4* __restrict__ o1,
                      const float4* __restrict__ o2,
                      const float*  __restrict__ desire,
                      float* __restrict__ out,
                      int n_rows) {
    const int lane = threadIdx.x & 31;
    const int wib  = threadIdx.x >> 5;
    const int wpb  = blockDim.x >> 5;
    const int wg   = blockIdx.x * wpb + wib;
    const int tw   = gridDim.x * wpb;

    const int g = lane >> 3;   // row within the 4-row tile (0..3)
    const int j = lane & 7;    // float4 slot within row: j, j+8, j+16, j+24

    double       l_inter = 0.0, l_des = 0.0;
    unsigned int l_cnt = 0u;
    const float margin_sq = 0.390625f;   // (1.25/2)^2

    const int n_tiles = n_rows >> 2;

    // Three register stages.
    float4 a00, a01, a02, a03, b00, b01, b02, b03;   // stage 0
    float4 a10, a11, a12, a13, b10, b11, b12, b13;   // stage 1
    float4 a20, a21, a22, a23, b20, b21, b22, b23;   // stage 2

    int t = wg;
    LOAD_TILE(t,          a00, a01, a02, a03, b00, b01, b02, b03);
    LOAD_TILE(t + tw,     a10, a11, a12, a13, b10, b11, b12, b13);
    LOAD_TILE(t + 2 * tw, a20, a21, a22, a23, b20, b21, b22, b23);

    while (t < n_tiles) {
        COMPUTE_TILE(t, a00, a01, a02, a03, b00, b01, b02, b03);
        LOAD_TILE(t + 3 * tw, a00, a01, a02, a03, b00, b01, b02, b03);
        t += tw;
        if (t >= n_tiles) break;

        COMPUTE_TILE(t, a10, a11, a12, a13, b10, b11, b12, b13);
        LOAD_TILE(t + 3 * tw, a10, a11, a12, a13, b10, b11, b12, b13);
        t += tw;
        if (t >= n_tiles) break;

        COMPUTE_TILE(t, a20, a21, a22, a23, b20, b21, b22, b23);
        LOAD_TILE(t + 3 * tw, a20, a21, a22, a23, b20, b21, b22, b23);
        t += tw;
    }

    // Tail rows (n_rows % 4), warp 0 only (N=262144 -> empty, kept generic).
    if (wg == 0) {
        for (int row = n_tiles * 4; row < n_rows; row++) {
            float s = 0.0f;
            if (g == 0) {
                const int base = row * 32 + j;
                #pragma unroll
                for (int k = 0; k < 4; k++) {
                    const float4 a = o1[base + 8 * k];
                    const float4 b = o2[base + 8 * k];
                    const float dx = a.x - b.x, dy = a.y - b.y;
                    const float dz = a.z - b.z, dw = a.w - b.w;
                    s += dx * dx + dy * dy + dz * dz + dw * dw;
                }
            }
            s += __shfl_xor_sync(0xffffffffu, s, 4);
            s += __shfl_xor_sync(0xffffffffu, s, 2);
            s += __shfl_xor_sync(0xffffffffu, s, 1);
            if (lane == 0) {
                const float dsr = desire[row];
                l_des += (double)dsr;
                if (s > margin_sq) { l_cnt += 1u; l_inter += (double)dsr; }
            }
        }
    }

    // Warp reduction (accumulators live on the j==0 lanes; reduce all 32).
    #pragma unroll
    for (int off = 16; off > 0; off >>= 1) {
        l_inter += __shfl_xor_sync(0xffffffffu, l_inter, off);
        l_des   += __shfl_xor_sync(0xffffffffu, l_des,   off);
        l_cnt   += __shfl_xor_sync(0xffffffffu, l_cnt,   off);
    }

    __shared__ double       s_i[8], s_d[8];
    __shared__ unsigned int s_c[8];
    __shared__ bool         s_last;
    if (lane == 0) { s_i[wib] = l_inter; s_d[wib] = l_des; s_c[wib] = l_cnt; }
    __syncthreads();

    if (threadIdx.x == 0) {
        double       bi = 0.0, bd = 0.0;
        unsigned int bc = 0u;
        for (int w = 0; w < wpb; w++) { bi += s_i[w]; bd += s_d[w]; bc += s_c[w]; }
        atomicAdd(&g_inter, bi);
        atomicAdd(&g_desire_sum, bd);
        atomicAdd(&g_count, (unsigned long long)bc);
        __threadfence();
        s_last = (atomicAdd(&g_ticket, 1u) == gridDim.x - 1);
    }
    __syncthreads();

    if (s_last && threadIdx.x == 0) {
        __threadfence();
        const double inter = atomicAdd(&g_inter, 0.0);
        const double des   = atomicAdd(&g_desire_sum, 0.0);
        const double cnt   = (double)atomicAdd(&g_count, 0ull);
        const double uni   = cnt + des - inter;
        out[0] = (float)((inter + 1e-6) / (uni + 1e-6));
        g_inter = 0.0;
        g_desire_sum = 0.0;
        g_count = 0ull;
        __threadfence();
        g_ticket = 0u;
    }
}

extern "C" void kernel_launch(void* const* d_in, const int* in_sizes, int n_in,
                              void* d_out, int out_size) {
    const float4* o1     = (const float4*)d_in[0];
    const float4* o2     = (const float4*)d_in[1];
    const float*  desire = (const float*)d_in[2];
    float*        out    = (float*)d_out;

    const int n_rows = in_sizes[2];   // N = 262144

    // 296 = 148 SMs x 2 blocks (launch_bounds clamps regs to fit 2/SM):
    // 16 warps/SM x 8 KB in flight each = 128 KB/SM of outstanding reads.
    fra_fused_kernel<<<296, 256>>>(o1, o2, desire, out, n_rows);
}